// round 17
// baseline (speedup 1.0000x reference)
#include <cuda_runtime.h>
#include <cstdint>

#define OUTP 7
#define CCH 256
#define NS 14                        // samples per axis
#define BINS 49
#define OUT_PER_BOX (CCH * BINS)     // 12544
#define CH_PER_CTA 16
#define NGROUPS (CCH / CH_PER_CTA)   // 16
#define THREADS 128
#define NWARPS (THREADS / 32)        // 4 warps -> 4*4 = 16 channels

// Fully warp-independent body. H, W compile-time so channel offsets fold into
// LDG immediates. x-tap prep is per-lane in registers; only the 7 y-param
// packs go through per-warp smem guarded by __syncwarp. No CTA barriers.
template<int H, int W>
__device__ __forceinline__ void roi_body(
    const float* __restrict__ base_ch,     // + this warp's channel offset
    float* __restrict__ out_g,
    int4* s_ro, float4* s_wy,              // this warp's 7-entry arrays
    float x1, float y1, float bw, float bh,
    int lane)
{
    constexpr int HW = H * W;

    // ---- per-lane x-tap prep (lanes 28..31 replicate tap 27, weight 0, so
    // their addresses stay inside the ROI column span: no extra sector) ----
    const int laneT = (lane < 28) ? lane : 27;
    const int isx   = laneT >> 1;          // x-sample index 0..13
    const int q     = laneT & 1;           // 0 = lo tap, 1 = hi tap
    int colb; float wxwb;
    {
        const int p  = isx >> 1;
        const int ss = isx & 1;
        const float gg = (float)p + ((float)ss + 0.5f) * 0.5f;
        const float coord = x1 + bw * gg;
        const float v = (coord > -1.0f && coord < (float)W) ? 1.0f : 0.0f;
        float cc  = fmaxf(coord, 0.0f);
        float low = floorf(cc);
        const float cap = (float)(W - 1);
        const bool at_edge = (low >= cap);
        low = fminf(low, cap);
        const float high = fminf(low + 1.0f, cap);
        if (at_edge) cc = low;
        const float frac = cc - low;
        const float w0 = (1.0f - frac) * v;
        const float w1 = frac * v;
        colb = q ? (int)high : (int)low;
        wxwb = (q ? w1 : w0) * 0.25f;       // fold subsample-mean 0.25
        if (lane >= 28) wxwb = 0.0f;
    }

    // ---- y prep: lanes 0..13 each handle one y-sample ----
    if (lane < NS) {
        const int i  = lane;
        const int p  = i >> 1;
        const int ss = i & 1;
        const float gg = (float)p + ((float)ss + 0.5f) * 0.5f;
        const float coord = y1 + bh * gg;
        const float v = (coord > -1.0f && coord < (float)H) ? 1.0f : 0.0f;
        float cc  = fmaxf(coord, 0.0f);
        float low = floorf(cc);
        const float cap = (float)(H - 1);
        const bool at_edge = (low >= cap);
        low = fminf(low, cap);
        const float high = fminf(low + 1.0f, cap);
        if (at_edge) cc = low;
        const float frac = cc - low;
        int*   rop = (int*)s_ro;
        float* wyp = (float*)s_wy;
        rop[4 * p + 2 * ss + 0] = (int)low  * W;
        rop[4 * p + 2 * ss + 1] = (int)high * W;
        wyp[4 * p + 2 * ss + 0] = (1.0f - frac) * v;
        wyp[4 * p + 2 * ss + 1] = frac * v;
    }
    __syncwarp();

    const float* const base0 = base_ch + colb;
    const bool writer = ((lane & 3) == 0) && (lane < 28);
    const int  pw     = lane >> 2;

    // Fully unrolled pipelined mainloop; k*HW offsets are LDG immediates.
    #pragma unroll
    for (int ph = 0; ph < OUTP; ++ph) {
        const int4   ro = s_ro[ph];
        const float4 wy = s_wy[ph];

        const float v00 = base0[ro.x + 0 * HW], v01 = base0[ro.y + 0 * HW],
                    v02 = base0[ro.z + 0 * HW], v03 = base0[ro.w + 0 * HW];
        const float v10 = base0[ro.x + 1 * HW], v11 = base0[ro.y + 1 * HW],
                    v12 = base0[ro.z + 1 * HW], v13 = base0[ro.w + 1 * HW];
        const float v20 = base0[ro.x + 2 * HW], v21 = base0[ro.y + 2 * HW],
                    v22 = base0[ro.z + 2 * HW], v23 = base0[ro.w + 2 * HW];
        const float v30 = base0[ro.x + 3 * HW], v31 = base0[ro.y + 3 * HW],
                    v32 = base0[ro.z + 3 * HW], v33 = base0[ro.w + 3 * HW];

        float a0 = wxwb * (wy.x * v00 + wy.y * v01 + wy.z * v02 + wy.w * v03);
        float a1 = wxwb * (wy.x * v10 + wy.y * v11 + wy.z * v12 + wy.w * v13);
        float a2 = wxwb * (wy.x * v20 + wy.y * v21 + wy.z * v22 + wy.w * v23);
        float a3 = wxwb * (wy.x * v30 + wy.y * v31 + wy.z * v32 + wy.w * v33);

        a0 += __shfl_xor_sync(0xffffffffu, a0, 1);
        a1 += __shfl_xor_sync(0xffffffffu, a1, 1);
        a2 += __shfl_xor_sync(0xffffffffu, a2, 1);
        a3 += __shfl_xor_sync(0xffffffffu, a3, 1);
        a0 += __shfl_xor_sync(0xffffffffu, a0, 2);
        a1 += __shfl_xor_sync(0xffffffffu, a1, 2);
        a2 += __shfl_xor_sync(0xffffffffu, a2, 2);
        a3 += __shfl_xor_sync(0xffffffffu, a3, 2);

        if (writer) {
            const int o = ph * OUTP + pw;
            out_g[0 * BINS + o] = a0;
            out_g[1 * BINS + o] = a1;
            out_g[2 * BINS + o] = a2;
            out_g[3 * BINS + o] = a3;
        }
    }
}

__global__ __launch_bounds__(THREADS, 12) void roi_pooler_kernel(
    const float* __restrict__ f0, const float* __restrict__ f1,
    const float* __restrict__ f2, const float* __restrict__ f3,
    const float* __restrict__ boxes, float* __restrict__ out)
{
    __shared__ int4   s_ro[NWARPS][OUTP];
    __shared__ float4 s_wy[NWARPS][OUTP];

    const int blk  = blockIdx.x;             // [0, 512*NGROUPS)
    const int n    = blk >> 4;               // box index [0,512)
    const int g    = blk & (NGROUPS - 1);    // channel group [0,16)
    const int tid  = threadIdx.x;
    const int lane = tid & 31;
    const int wid  = tid >> 5;

    // ---- geometry: every lane computes redundantly (broadcast loads, no sync)
    const int b = n >> 8;
    const float bx1 = __ldg(&boxes[n * 4 + 0]);
    const float by1 = __ldg(&boxes[n * 4 + 1]);
    const float bx2 = __ldg(&boxes[n * 4 + 2]);
    const float by2 = __ldg(&boxes[n * 4 + 3]);
    const float area = (bx2 - bx1) * (by2 - by1);
    float lvlf = floorf(4.0f + log2f(sqrtf(area) * (1.0f / 224.0f) + 1e-8f));
    lvlf = fminf(fmaxf(lvlf, 2.0f), 5.0f);
    const int lvl = (int)lvlf - 2;

    const size_t choff = (size_t)b * CCH + (size_t)g * CH_PER_CTA + (size_t)(wid * 4);
    float* const out_g = out + (size_t)n * OUT_PER_BOX
                             + (size_t)g * CH_PER_CTA * BINS
                             + (size_t)(wid * 4) * BINS;

    // warp-uniform dispatch (same box for all warps of the CTA)
    switch (lvl) {
        case 0: {
            constexpr float sc = 0.25f;
            const float x1 = bx1 * sc, y1 = by1 * sc;
            const float bw = fmaxf(bx2 * sc - x1, 1.0f) * (1.0f / OUTP);
            const float bh = fmaxf(by2 * sc - y1, 1.0f) * (1.0f / OUTP);
            roi_body<200, 200>(f0 + choff * (200 * 200), out_g,
                               s_ro[wid], s_wy[wid], x1, y1, bw, bh, lane);
        } break;
        case 1: {
            constexpr float sc = 0.125f;
            const float x1 = bx1 * sc, y1 = by1 * sc;
            const float bw = fmaxf(bx2 * sc - x1, 1.0f) * (1.0f / OUTP);
            const float bh = fmaxf(by2 * sc - y1, 1.0f) * (1.0f / OUTP);
            roi_body<100, 100>(f1 + choff * (100 * 100), out_g,
                               s_ro[wid], s_wy[wid], x1, y1, bw, bh, lane);
        } break;
        case 2: {
            constexpr float sc = 0.0625f;
            const float x1 = bx1 * sc, y1 = by1 * sc;
            const float bw = fmaxf(bx2 * sc - x1, 1.0f) * (1.0f / OUTP);
            const float bh = fmaxf(by2 * sc - y1, 1.0f) * (1.0f / OUTP);
            roi_body<50, 50>(f2 + choff * (50 * 50), out_g,
                             s_ro[wid], s_wy[wid], x1, y1, bw, bh, lane);
        } break;
        default: {
            constexpr float sc = 0.03125f;
            const float x1 = bx1 * sc, y1 = by1 * sc;
            const float bw = fmaxf(bx2 * sc - x1, 1.0f) * (1.0f / OUTP);
            const float bh = fmaxf(by2 * sc - y1, 1.0f) * (1.0f / OUTP);
            roi_body<25, 25>(f3 + choff * (25 * 25), out_g,
                             s_ro[wid], s_wy[wid], x1, y1, bw, bh, lane);
        } break;
    }
}

extern "C" void kernel_launch(void* const* d_in, const int* in_sizes, int n_in,
                              void* d_out, int out_size) {
    const float* f0    = (const float*)d_in[0];
    const float* f1    = (const float*)d_in[1];
    const float* f2    = (const float*)d_in[2];
    const float* f3    = (const float*)d_in[3];
    const float* boxes = (const float*)d_in[4];
    float* out = (float*)d_out;

    roi_pooler_kernel<<<512 * NGROUPS, THREADS>>>(f0, f1, f2, f3, boxes, out);
}